// round 3
// baseline (speedup 1.0000x reference)
#include <cuda_runtime.h>
#include <cstdint>

#define NN 50000
#define NE 800000
#define F  128

// ---------------- device scratch (no allocations allowed) -------------------
__device__ int   g_deg_out_i[NN];
__device__ int   g_deg_in_i[NN];
__device__ int   g_row_start[NN];
__device__ int   g_cursor[NN];
__device__ float g_scale_out[NN];     // rsqrt(max(deg_out,1))
__device__ int   g_perm_src[NE];      // src indices grouped by dst
__device__ float g_h[NN * F];         // normalized aggregated features

// ---------------------------------------------------------------------------
// 1) zero degree arrays
// ---------------------------------------------------------------------------
__global__ void zero_kernel() {
    int i = blockIdx.x * blockDim.x + threadIdx.x;
    if (i < NN) { g_deg_out_i[i] = 0; g_deg_in_i[i] = 0; }
}

// ---------------------------------------------------------------------------
// 2) degree histograms
// ---------------------------------------------------------------------------
__global__ void deg_kernel(const int* __restrict__ src, const int* __restrict__ dst) {
    int e = blockIdx.x * blockDim.x + threadIdx.x;
    if (e < NE) {
        atomicAdd(&g_deg_out_i[src[e]], 1);
        atomicAdd(&g_deg_in_i[dst[e]], 1);
    }
}

// ---------------------------------------------------------------------------
// 3) single-block scan -> row_start / cursor / scale_out
// ---------------------------------------------------------------------------
#define SCAN_T 1024
#define CHUNK  ((NN + SCAN_T - 1) / SCAN_T)   // 49

__global__ void __launch_bounds__(SCAN_T)
scan_kernel() {
    __shared__ int part[SCAN_T];
    int t = threadIdx.x;
    int base = t * CHUNK;

    int s = 0;
    for (int i = 0; i < CHUNK; i++) {
        int idx = base + i;
        if (idx < NN) s += g_deg_in_i[idx];
    }
    part[t] = s;
    __syncthreads();
    for (int off = 1; off < SCAN_T; off <<= 1) {
        int v = (t >= off) ? part[t - off] : 0;
        __syncthreads();
        part[t] += v;
        __syncthreads();
    }
    int running = part[t] - s;
    for (int i = 0; i < CHUNK; i++) {
        int idx = base + i;
        if (idx < NN) {
            g_row_start[idx] = running;
            g_cursor[idx]    = running;
            running += g_deg_in_i[idx];
            g_scale_out[idx] = rsqrtf(fmaxf((float)g_deg_out_i[idx], 1.0f));
        }
    }
}

// ---------------------------------------------------------------------------
// 4) counting-sort scatter (2 edges per thread for ILP)
// ---------------------------------------------------------------------------
__global__ void scatter_kernel(const int* __restrict__ src, const int* __restrict__ dst) {
    int t = blockIdx.x * blockDim.x + threadIdx.x;
    int e0 = t * 2;
    if (e0 + 1 < NE) {
        int d0 = dst[e0], d1 = dst[e0 + 1];
        int s0 = src[e0], s1 = src[e0 + 1];
        int p0 = atomicAdd(&g_cursor[d0], 1);
        int p1 = atomicAdd(&g_cursor[d1], 1);
        g_perm_src[p0] = s0;
        g_perm_src[p1] = s1;
    } else if (e0 < NE) {
        int p0 = atomicAdd(&g_cursor[dst[e0]], 1);
        g_perm_src[p0] = src[e0];
    }
}

// ---------------------------------------------------------------------------
// 5) CSR aggregation: one warp per node, both norms folded in.
//    No smem -> full occupancy; unroll-4 edge loop -> 4 LDG.128 in flight.
// ---------------------------------------------------------------------------
__global__ void __launch_bounds__(256)
agg_kernel(const float* __restrict__ x) {
    int gtid = blockIdx.x * blockDim.x + threadIdx.x;
    int node = gtid >> 5;
    int lane = threadIdx.x & 31;
    if (node >= NN) return;

    int start = g_row_start[node];
    int len   = g_deg_in_i[node];
    const int* ps = g_perm_src + start;
    const float4* x4 = reinterpret_cast<const float4*>(x);

    float4 acc = make_float4(0.f, 0.f, 0.f, 0.f);
    int i = 0;
    for (; i + 4 <= len; i += 4) {
        int s0 = ps[i], s1 = ps[i + 1], s2 = ps[i + 2], s3 = ps[i + 3];
        float c0 = g_scale_out[s0], c1 = g_scale_out[s1];
        float c2 = g_scale_out[s2], c3 = g_scale_out[s3];
        float4 a0 = x4[(size_t)s0 * 32 + lane];
        float4 a1 = x4[(size_t)s1 * 32 + lane];
        float4 a2 = x4[(size_t)s2 * 32 + lane];
        float4 a3 = x4[(size_t)s3 * 32 + lane];
        acc.x += c0 * a0.x; acc.y += c0 * a0.y; acc.z += c0 * a0.z; acc.w += c0 * a0.w;
        acc.x += c1 * a1.x; acc.y += c1 * a1.y; acc.z += c1 * a1.z; acc.w += c1 * a1.w;
        acc.x += c2 * a2.x; acc.y += c2 * a2.y; acc.z += c2 * a2.z; acc.w += c2 * a2.w;
        acc.x += c3 * a3.x; acc.y += c3 * a3.y; acc.z += c3 * a3.z; acc.w += c3 * a3.w;
    }
    for (; i < len; i++) {
        int s0 = ps[i];
        float c0 = g_scale_out[s0];
        float4 a0 = x4[(size_t)s0 * 32 + lane];
        acc.x += c0 * a0.x; acc.y += c0 * a0.y; acc.z += c0 * a0.z; acc.w += c0 * a0.w;
    }
    float inv = rsqrtf(fmaxf((float)len, 1.0f));   // right norm (commutes with @W)
    acc.x *= inv; acc.y *= inv; acc.z *= inv; acc.w *= inv;
    reinterpret_cast<float4*>(g_h + (size_t)node * F)[lane] = acc;
}

// ---------------------------------------------------------------------------
// 6) GEMM (h @ W) + bias, packed f32x2 FMA (Blackwell dual-fp32 path).
//    Block 256 thr / 8 warps, 64 rows (8 per warp). W + 64-row H tile in smem.
//    Lane owns cols [4l..4l+3] as two f32x2 pairs.
// ---------------------------------------------------------------------------
__device__ __forceinline__ uint64_t fma2(uint64_t a, uint64_t b, uint64_t c) {
    uint64_t d;
    asm("fma.rn.f32x2 %0, %1, %2, %3;" : "=l"(d) : "l"(a), "l"(b), "l"(c));
    return d;
}
__device__ __forceinline__ uint64_t pack2(float v) {
    uint64_t d;
    asm("mov.b64 %0, {%1, %1};" : "=l"(d) : "f"(v));
    return d;
}

__global__ void __launch_bounds__(256, 2)
gemm_kernel(const float* __restrict__ weight, const float* __restrict__ bias,
            float* __restrict__ out) {
    extern __shared__ float sm[];
    float* Wsh = sm;             // 128*128 = 64KB
    float* Hsh = sm + F * F;     // 64*128  = 32KB

    int tid  = threadIdx.x;
    int warp = tid >> 5;
    int lane = tid & 31;
    int row0 = blockIdx.x * 64;

    for (int i = tid; i < F * F / 4; i += 256)
        reinterpret_cast<float4*>(Wsh)[i] = reinterpret_cast<const float4*>(weight)[i];
    for (int i = tid; i < 64 * F / 4; i += 256) {
        int gidx = row0 * (F / 4) + i;
        float4 v = make_float4(0.f, 0.f, 0.f, 0.f);
        if (gidx < NN * (F / 4))
            v = reinterpret_cast<const float4*>(g_h)[gidx];
        reinterpret_cast<float4*>(Hsh)[i] = v;
    }
    __syncthreads();

    int r0 = warp * 8;
    uint64_t acc0[8], acc1[8];
#pragma unroll
    for (int r = 0; r < 8; r++) { acc0[r] = 0ull; acc1[r] = 0ull; }

#pragma unroll 4
    for (int k = 0; k < F; k++) {
        // 16B per lane, consecutive -> conflict-free LDS.128; pairs pre-packed
        ulonglong2 wv = reinterpret_cast<ulonglong2*>(Wsh)[k * 32 + lane];
#pragma unroll
        for (int r = 0; r < 8; r++) {
            uint64_t hh = pack2(Hsh[(r0 + r) * F + k]);   // warp broadcast + pack
            acc0[r] = fma2(hh, wv.x, acc0[r]);
            acc1[r] = fma2(hh, wv.y, acc1[r]);
        }
    }

    float4 bv = reinterpret_cast<const float4*>(bias)[lane];
#pragma unroll
    for (int r = 0; r < 8; r++) {
        int row = row0 + r0 + r;
        if (row < NN) {
            float2 p0 = *reinterpret_cast<float2*>(&acc0[r]);
            float2 p1 = *reinterpret_cast<float2*>(&acc1[r]);
            float4 o;
            o.x = p0.x + bv.x;
            o.y = p0.y + bv.y;
            o.z = p1.x + bv.z;
            o.w = p1.y + bv.w;
            reinterpret_cast<float4*>(out + (size_t)row * F)[lane] = o;
        }
    }
}

// ---------------------------------------------------------------------------
extern "C" void kernel_launch(void* const* d_in, const int* in_sizes, int n_in,
                              void* d_out, int out_size) {
    const float* x      = (const float*)d_in[0];
    const int*   src    = (const int*)d_in[1];
    const int*   dst    = (const int*)d_in[2];
    const float* weight = (const float*)d_in[3];
    const float* bias   = (const float*)d_in[4];
    float*       out    = (float*)d_out;

    zero_kernel<<<(NN + 255) / 256, 256>>>();
    deg_kernel<<<(NE + 255) / 256, 256>>>(src, dst);
    scan_kernel<<<1, SCAN_T>>>();
    scatter_kernel<<<((NE + 1) / 2 + 255) / 256, 256>>>(src, dst);

    {
        long long threads = (long long)NN * 32;
        int blocks = (int)((threads + 255) / 256);
        agg_kernel<<<blocks, 256>>>(x);
    }
    {
        int smem = (F * F + 64 * F) * (int)sizeof(float);  // 98304 B
        cudaFuncSetAttribute(gemm_kernel, cudaFuncAttributeMaxDynamicSharedMemorySize, smem);
        gemm_kernel<<<(NN + 63) / 64, 256, smem>>>(weight, bias, out);
    }
}

// round 4
// speedup vs baseline: 2.7431x; 2.7431x over previous
#include <cuda_runtime.h>

#define NN 50000
#define NE 800000
#define F  128
#define SCAN_B 256
#define NBLK ((NN + SCAN_B - 1) / SCAN_B)   // 196

// ---------------- device scratch (no allocations allowed) -------------------
__device__ int   g_deg_out_i[NN];
__device__ int   g_deg_in_i[NN];
__device__ int   g_row_start[NN];
__device__ int   g_cursor[NN];
__device__ float g_scale_out[NN];     // rsqrt(max(deg_out,1))
__device__ int   g_perm_src[NE];      // src indices grouped by dst
__device__ float g_h[NN * F];         // aggregated + right-normalized features
__device__ int   g_scan_tmp[NN];
__device__ int   g_block_sums[NBLK];

// ---------------------------------------------------------------------------
// 1) zero degree arrays
// ---------------------------------------------------------------------------
__global__ void zero_kernel() {
    int i = blockIdx.x * blockDim.x + threadIdx.x;
    if (i < NN) { g_deg_out_i[i] = 0; g_deg_in_i[i] = 0; }
}

// ---------------------------------------------------------------------------
// 2) degree histograms
// ---------------------------------------------------------------------------
__global__ void deg_kernel(const int* __restrict__ src, const int* __restrict__ dst) {
    int e = blockIdx.x * blockDim.x + threadIdx.x;
    if (e < NE) {
        atomicAdd(&g_deg_out_i[src[e]], 1);
        atomicAdd(&g_deg_in_i[dst[e]], 1);
    }
}

// ---------------------------------------------------------------------------
// 3) multi-block exclusive scan of deg_in (3 tiny kernels)
// ---------------------------------------------------------------------------
__global__ void __launch_bounds__(SCAN_B)
scan1_kernel() {
    int idx  = blockIdx.x * SCAN_B + threadIdx.x;
    int lane = threadIdx.x & 31;
    int w    = threadIdx.x >> 5;
    int v    = (idx < NN) ? g_deg_in_i[idx] : 0;

    int x = v;
#pragma unroll
    for (int o = 1; o < 32; o <<= 1) {
        int t = __shfl_up_sync(0xffffffffu, x, o);
        if (lane >= o) x += t;
    }
    __shared__ int wsum[8];
    if (lane == 31) wsum[w] = x;
    __syncthreads();
    if (threadIdx.x < 8) {
        int s = wsum[threadIdx.x];
#pragma unroll
        for (int o = 1; o < 8; o <<= 1) {
            int t = __shfl_up_sync(0xffu, s, o);
            if ((int)threadIdx.x >= o) s += t;
        }
        wsum[threadIdx.x] = s;
    }
    __syncthreads();
    int woff = (w > 0) ? wsum[w - 1] : 0;
    if (idx < NN) g_scan_tmp[idx] = woff + x - v;      // exclusive within block
    if (threadIdx.x == SCAN_B - 1) g_block_sums[blockIdx.x] = wsum[7];
}

__global__ void __launch_bounds__(SCAN_B)
scan2_kernel() {
    int t    = threadIdx.x;
    int lane = t & 31;
    int w    = t >> 5;
    int v    = (t < NBLK) ? g_block_sums[t] : 0;
    int x = v;
#pragma unroll
    for (int o = 1; o < 32; o <<= 1) {
        int tt = __shfl_up_sync(0xffffffffu, x, o);
        if (lane >= o) x += tt;
    }
    __shared__ int wsum[8];
    if (lane == 31) wsum[w] = x;
    __syncthreads();
    if (t < 8) {
        int s = wsum[t];
#pragma unroll
        for (int o = 1; o < 8; o <<= 1) {
            int tt = __shfl_up_sync(0xffu, s, o);
            if (t >= o) s += tt;
        }
        wsum[t] = s;
    }
    __syncthreads();
    int woff = (w > 0) ? wsum[w - 1] : 0;
    if (t < NBLK) g_block_sums[t] = woff + x - v;       // exclusive block offsets
}

__global__ void __launch_bounds__(SCAN_B)
scan3_kernel() {
    int idx = blockIdx.x * SCAN_B + threadIdx.x;
    if (idx < NN) {
        int rs = g_scan_tmp[idx] + g_block_sums[blockIdx.x];
        g_row_start[idx] = rs;
        g_cursor[idx]    = rs;
        g_scale_out[idx] = rsqrtf(fmaxf((float)g_deg_out_i[idx], 1.0f));
    }
}

// ---------------------------------------------------------------------------
// 4) counting-sort scatter: group src indices by dst (2 edges/thread ILP)
// ---------------------------------------------------------------------------
__global__ void scatter_kernel(const int* __restrict__ src, const int* __restrict__ dst) {
    int t = blockIdx.x * blockDim.x + threadIdx.x;
    int e0 = t * 2;
    if (e0 + 1 < NE) {
        int d0 = dst[e0], d1 = dst[e0 + 1];
        int s0 = src[e0], s1 = src[e0 + 1];
        int p0 = atomicAdd(&g_cursor[d0], 1);
        int p1 = atomicAdd(&g_cursor[d1], 1);
        g_perm_src[p0] = s0;
        g_perm_src[p1] = s1;
    } else if (e0 < NE) {
        int p0 = atomicAdd(&g_cursor[dst[e0]], 1);
        g_perm_src[p0] = src[e0];
    }
}

// ---------------------------------------------------------------------------
// 5) CSR aggregation: one warp per node, both norms folded in.
// ---------------------------------------------------------------------------
__global__ void __launch_bounds__(256)
agg_kernel(const float* __restrict__ x) {
    int gtid = blockIdx.x * blockDim.x + threadIdx.x;
    int node = gtid >> 5;
    int lane = threadIdx.x & 31;
    if (node >= NN) return;

    int start = g_row_start[node];
    int len   = g_deg_in_i[node];
    const int* ps = g_perm_src + start;
    const float4* x4 = reinterpret_cast<const float4*>(x);

    float4 acc = make_float4(0.f, 0.f, 0.f, 0.f);
    int i = 0;
    for (; i + 4 <= len; i += 4) {
        int s0 = ps[i], s1 = ps[i + 1], s2 = ps[i + 2], s3 = ps[i + 3];
        float c0 = g_scale_out[s0], c1 = g_scale_out[s1];
        float c2 = g_scale_out[s2], c3 = g_scale_out[s3];
        float4 a0 = x4[(size_t)s0 * 32 + lane];
        float4 a1 = x4[(size_t)s1 * 32 + lane];
        float4 a2 = x4[(size_t)s2 * 32 + lane];
        float4 a3 = x4[(size_t)s3 * 32 + lane];
        acc.x += c0 * a0.x; acc.y += c0 * a0.y; acc.z += c0 * a0.z; acc.w += c0 * a0.w;
        acc.x += c1 * a1.x; acc.y += c1 * a1.y; acc.z += c1 * a1.z; acc.w += c1 * a1.w;
        acc.x += c2 * a2.x; acc.y += c2 * a2.y; acc.z += c2 * a2.z; acc.w += c2 * a2.w;
        acc.x += c3 * a3.x; acc.y += c3 * a3.y; acc.z += c3 * a3.z; acc.w += c3 * a3.w;
    }
    for (; i < len; i++) {
        int s0 = ps[i];
        float c0 = g_scale_out[s0];
        float4 a0 = x4[(size_t)s0 * 32 + lane];
        acc.x += c0 * a0.x; acc.y += c0 * a0.y; acc.z += c0 * a0.z; acc.w += c0 * a0.w;
    }
    float inv = rsqrtf(fmaxf((float)len, 1.0f));   // right norm (commutes with @W)
    acc.x *= inv; acc.y *= inv; acc.z *= inv; acc.w *= inv;
    reinterpret_cast<float4*>(g_h + (size_t)node * F)[lane] = acc;
}

// ---------------------------------------------------------------------------
// 6) GEMM (h @ W) + bias — R1-proven structure.
//    Block 256 thr / 8 warps, 32 rows (4 per warp). W + H tile in smem.
// ---------------------------------------------------------------------------
__global__ void __launch_bounds__(256, 2)
gemm_kernel(const float* __restrict__ weight, const float* __restrict__ bias,
            float* __restrict__ out) {
    extern __shared__ float sm[];
    float* Wsh = sm;            // 128*128 = 64KB
    float* Hsh = sm + F * F;    // 32*128  = 16KB

    int tid  = threadIdx.x;
    int row0 = blockIdx.x * 32;

    for (int i = tid; i < F * F / 4; i += 256)
        reinterpret_cast<float4*>(Wsh)[i] = reinterpret_cast<const float4*>(weight)[i];
    for (int i = tid; i < 32 * F / 4; i += 256) {
        int gidx = row0 * (F / 4) + i;
        float4 v = make_float4(0.f, 0.f, 0.f, 0.f);
        if (gidx < NN * (F / 4))
            v = reinterpret_cast<const float4*>(g_h)[gidx];
        reinterpret_cast<float4*>(Hsh)[i] = v;
    }
    __syncthreads();

    int warp = tid >> 5;
    int lane = tid & 31;
    int r0 = warp * 4;

    float4 acc[4];
#pragma unroll
    for (int r = 0; r < 4; r++) acc[r] = make_float4(0.f, 0.f, 0.f, 0.f);

#pragma unroll 4
    for (int k = 0; k < F; k++) {
        float4 wv = reinterpret_cast<float4*>(Wsh)[k * 32 + lane];  // conflict-free
#pragma unroll
        for (int r = 0; r < 4; r++) {
            float hv = Hsh[(r0 + r) * F + k];                        // warp broadcast
            acc[r].x += hv * wv.x;
            acc[r].y += hv * wv.y;
            acc[r].z += hv * wv.z;
            acc[r].w += hv * wv.w;
        }
    }

    float4 bv = reinterpret_cast<const float4*>(bias)[lane];
#pragma unroll
    for (int r = 0; r < 4; r++) {
        int row = row0 + r0 + r;
        if (row < NN) {
            float4 o;
            o.x = acc[r].x + bv.x;
            o.y = acc[r].y + bv.y;
            o.z = acc[r].z + bv.z;
            o.w = acc[r].w + bv.w;
            reinterpret_cast<float4*>(out + (size_t)row * F)[lane] = o;
        }
    }
}

// ---------------------------------------------------------------------------
extern "C" void kernel_launch(void* const* d_in, const int* in_sizes, int n_in,
                              void* d_out, int out_size) {
    const float* x      = (const float*)d_in[0];
    const int*   src    = (const int*)d_in[1];
    const int*   dst    = (const int*)d_in[2];
    const float* weight = (const float*)d_in[3];
    const float* bias   = (const float*)d_in[4];
    float*       out    = (float*)d_out;

    zero_kernel<<<(NN + 255) / 256, 256>>>();
    deg_kernel<<<(NE + 255) / 256, 256>>>(src, dst);
    scan1_kernel<<<NBLK, SCAN_B>>>();
    scan2_kernel<<<1, SCAN_B>>>();
    scan3_kernel<<<NBLK, SCAN_B>>>();
    scatter_kernel<<<((NE + 1) / 2 + 255) / 256, 256>>>(src, dst);

    {
        long long threads = (long long)NN * 32;
        int blocks = (int)((threads + 255) / 256);
        agg_kernel<<<blocks, 256>>>(x);
    }
    {
        int smem = (F * F + 32 * F) * (int)sizeof(float);  // 81920 B
        cudaFuncSetAttribute(gemm_kernel, cudaFuncAttributeMaxDynamicSharedMemorySize, smem);
        gemm_kernel<<<(NN + 31) / 32, 256, smem>>>(weight, bias, out);
    }
}

// round 5
// speedup vs baseline: 2.8902x; 1.0536x over previous
#include <cuda_runtime.h>
#include <cstdint>

#define NN 50000
#define NE 800000
#define F  128
#define SCAN_B 256
#define NBLK ((NN + SCAN_B - 1) / SCAN_B)   // 196

// GEMM tiling
#define BM   128          // rows per block
#define SW   132          // padded smem row stride (floats) -> conflict-free frags

// ---------------- device scratch (no allocations allowed) -------------------
__device__ int   g_deg_out_i[NN];
__device__ int   g_deg_in_i[NN];
__device__ int   g_row_start[NN];
__device__ int   g_cursor[NN];
__device__ float g_scale_out[NN];
__device__ int   g_perm_src[NE];
__device__ float g_h[NN * F];
__device__ int   g_scan_tmp[NN];
__device__ int   g_block_sums[NBLK];
__device__ float g_Whi[F * F];       // tf32-rounded weight
__device__ float g_Wlo[F * F];       // residual (tf32-rounded)

// ---------------------------------------------------------------------------
__global__ void zero_kernel() {
    int i = blockIdx.x * blockDim.x + threadIdx.x;
    if (i < NN) { g_deg_out_i[i] = 0; g_deg_in_i[i] = 0; }
}

__global__ void deg_kernel(const int* __restrict__ src, const int* __restrict__ dst) {
    int e = blockIdx.x * blockDim.x + threadIdx.x;
    if (e < NE) {
        atomicAdd(&g_deg_out_i[src[e]], 1);
        atomicAdd(&g_deg_in_i[dst[e]], 1);
    }
}

// ---------------------------------------------------------------------------
// multi-block exclusive scan of deg_in
// ---------------------------------------------------------------------------
__global__ void __launch_bounds__(SCAN_B)
scan1_kernel() {
    int idx  = blockIdx.x * SCAN_B + threadIdx.x;
    int lane = threadIdx.x & 31;
    int w    = threadIdx.x >> 5;
    int v    = (idx < NN) ? g_deg_in_i[idx] : 0;
    int x = v;
#pragma unroll
    for (int o = 1; o < 32; o <<= 1) {
        int t = __shfl_up_sync(0xffffffffu, x, o);
        if (lane >= o) x += t;
    }
    __shared__ int wsum[8];
    if (lane == 31) wsum[w] = x;
    __syncthreads();
    if (threadIdx.x < 8) {
        int s = wsum[threadIdx.x];
#pragma unroll
        for (int o = 1; o < 8; o <<= 1) {
            int t = __shfl_up_sync(0xffu, s, o);
            if ((int)threadIdx.x >= o) s += t;
        }
        wsum[threadIdx.x] = s;
    }
    __syncthreads();
    int woff = (w > 0) ? wsum[w - 1] : 0;
    if (idx < NN) g_scan_tmp[idx] = woff + x - v;
    if (threadIdx.x == SCAN_B - 1) g_block_sums[blockIdx.x] = wsum[7];
}

__global__ void __launch_bounds__(SCAN_B)
scan2_kernel() {
    int t    = threadIdx.x;
    int lane = t & 31;
    int w    = t >> 5;
    int v    = (t < NBLK) ? g_block_sums[t] : 0;
    int x = v;
#pragma unroll
    for (int o = 1; o < 32; o <<= 1) {
        int tt = __shfl_up_sync(0xffffffffu, x, o);
        if (lane >= o) x += tt;
    }
    __shared__ int wsum[8];
    if (lane == 31) wsum[w] = x;
    __syncthreads();
    if (t < 8) {
        int s = wsum[t];
#pragma unroll
        for (int o = 1; o < 8; o <<= 1) {
            int tt = __shfl_up_sync(0xffu, s, o);
            if (t >= o) s += tt;
        }
        wsum[t] = s;
    }
    __syncthreads();
    int woff = (w > 0) ? wsum[w - 1] : 0;
    if (t < NBLK) g_block_sums[t] = woff + x - v;
}

__global__ void __launch_bounds__(SCAN_B)
scan3_kernel() {
    int idx = blockIdx.x * SCAN_B + threadIdx.x;
    if (idx < NN) {
        int rs = g_scan_tmp[idx] + g_block_sums[blockIdx.x];
        g_row_start[idx] = rs;
        g_cursor[idx]    = rs;
        g_scale_out[idx] = rsqrtf(fmaxf((float)g_deg_out_i[idx], 1.0f));
    }
}

// ---------------------------------------------------------------------------
__global__ void scatter_kernel(const int* __restrict__ src, const int* __restrict__ dst) {
    int t = blockIdx.x * blockDim.x + threadIdx.x;
    int e0 = t * 2;
    if (e0 + 1 < NE) {
        int d0 = dst[e0], d1 = dst[e0 + 1];
        int s0 = src[e0], s1 = src[e0 + 1];
        int p0 = atomicAdd(&g_cursor[d0], 1);
        int p1 = atomicAdd(&g_cursor[d1], 1);
        g_perm_src[p0] = s0;
        g_perm_src[p1] = s1;
    } else if (e0 < NE) {
        int p0 = atomicAdd(&g_cursor[dst[e0]], 1);
        g_perm_src[p0] = src[e0];
    }
}

// ---------------------------------------------------------------------------
// CSR aggregation: one warp per node, both norms folded in.
// ---------------------------------------------------------------------------
__global__ void __launch_bounds__(256)
agg_kernel(const float* __restrict__ x) {
    int gtid = blockIdx.x * blockDim.x + threadIdx.x;
    int node = gtid >> 5;
    int lane = threadIdx.x & 31;
    if (node >= NN) return;

    int start = g_row_start[node];
    int len   = g_deg_in_i[node];
    const int* ps = g_perm_src + start;
    const float4* x4 = reinterpret_cast<const float4*>(x);

    float4 acc = make_float4(0.f, 0.f, 0.f, 0.f);
    int i = 0;
    for (; i + 4 <= len; i += 4) {
        int s0 = ps[i], s1 = ps[i + 1], s2 = ps[i + 2], s3 = ps[i + 3];
        float c0 = g_scale_out[s0], c1 = g_scale_out[s1];
        float c2 = g_scale_out[s2], c3 = g_scale_out[s3];
        float4 a0 = x4[(size_t)s0 * 32 + lane];
        float4 a1 = x4[(size_t)s1 * 32 + lane];
        float4 a2 = x4[(size_t)s2 * 32 + lane];
        float4 a3 = x4[(size_t)s3 * 32 + lane];
        acc.x += c0 * a0.x; acc.y += c0 * a0.y; acc.z += c0 * a0.z; acc.w += c0 * a0.w;
        acc.x += c1 * a1.x; acc.y += c1 * a1.y; acc.z += c1 * a1.z; acc.w += c1 * a1.w;
        acc.x += c2 * a2.x; acc.y += c2 * a2.y; acc.z += c2 * a2.z; acc.w += c2 * a2.w;
        acc.x += c3 * a3.x; acc.y += c3 * a3.y; acc.z += c3 * a3.z; acc.w += c3 * a3.w;
    }
    for (; i < len; i++) {
        int s0 = ps[i];
        float c0 = g_scale_out[s0];
        float4 a0 = x4[(size_t)s0 * 32 + lane];
        acc.x += c0 * a0.x; acc.y += c0 * a0.y; acc.z += c0 * a0.z; acc.w += c0 * a0.w;
    }
    float inv = rsqrtf(fmaxf((float)len, 1.0f));
    acc.x *= inv; acc.y *= inv; acc.z *= inv; acc.w *= inv;
    reinterpret_cast<float4*>(g_h + (size_t)node * F)[lane] = acc;
}

// ---------------------------------------------------------------------------
// W split: hi = tf32(w), lo = tf32(w - hi)
// ---------------------------------------------------------------------------
__device__ __forceinline__ float to_tf32(float v) {
    uint32_t b;
    asm("cvt.rna.tf32.f32 %0, %1;" : "=r"(b) : "f"(v));
    return __uint_as_float(b);
}

__global__ void wsplit_kernel(const float* __restrict__ weight) {
    int i = blockIdx.x * blockDim.x + threadIdx.x;
    if (i < F * F) {
        float w  = weight[i];
        float hi = to_tf32(w);
        g_Whi[i] = hi;
        g_Wlo[i] = to_tf32(w - hi);
    }
}

// ---------------------------------------------------------------------------
// Tensor-core GEMM (3xTF32): out = h @ W + bias
// Block: 256 thr / 8 warps, 128 rows. Warp w: rows [16w, 16w+16) x all 128 cols.
// smem: Whi[128][132], Wlo[128][132], Hs[128][132], bias[128]
// ---------------------------------------------------------------------------
__device__ __forceinline__ void mma_tf32(float& d0, float& d1, float& d2, float& d3,
                                         uint32_t a0, uint32_t a1, uint32_t a2, uint32_t a3,
                                         uint32_t b0, uint32_t b1) {
    asm volatile(
        "mma.sync.aligned.m16n8k8.row.col.f32.tf32.tf32.f32 "
        "{%0,%1,%2,%3}, {%4,%5,%6,%7}, {%8,%9}, {%0,%1,%2,%3};"
        : "+f"(d0), "+f"(d1), "+f"(d2), "+f"(d3)
        : "r"(a0), "r"(a1), "r"(a2), "r"(a3), "r"(b0), "r"(b1));
}

__global__ void __launch_bounds__(256, 1)
gemm_tc_kernel(const float* __restrict__ bias, float* __restrict__ out) {
    extern __shared__ float sm[];
    float* Whs = sm;                    // F * SW
    float* Wls = Whs + F * SW;          // F * SW
    float* Hs  = Wls + F * SW;          // BM * SW
    float* Bs  = Hs + BM * SW;          // F

    int tid  = threadIdx.x;
    int row0 = blockIdx.x * BM;

    // stage W hi/lo + H tile (padded rows; float4 stores, 528B row pitch is 16B-aligned)
    for (int i = tid; i < F * (F / 4); i += 256) {
        int r = i / (F / 4), c4 = i % (F / 4);
        float4 vh = reinterpret_cast<const float4*>(g_Whi)[r * (F / 4) + c4];
        float4 vl = reinterpret_cast<const float4*>(g_Wlo)[r * (F / 4) + c4];
        reinterpret_cast<float4*>(&Whs[r * SW + c4 * 4])[0] = vh;
        reinterpret_cast<float4*>(&Wls[r * SW + c4 * 4])[0] = vl;
    }
    for (int i = tid; i < BM * (F / 4); i += 256) {
        int r = i / (F / 4), c4 = i % (F / 4);
        float4 v = make_float4(0.f, 0.f, 0.f, 0.f);
        int grow = row0 + r;
        if (grow < NN)
            v = reinterpret_cast<const float4*>(g_h)[grow * (F / 4) + c4];
        reinterpret_cast<float4*>(&Hs[r * SW + c4 * 4])[0] = v;
    }
    if (tid < F) Bs[tid] = bias[tid];
    __syncthreads();

    int warp = tid >> 5;
    int lane = tid & 31;
    int gid  = lane >> 2;     // 0..7
    int tg   = lane & 3;      // 0..3
    int rb   = warp * 16;     // warp's smem row base

    float d[16][4];
#pragma unroll
    for (int nt = 0; nt < 16; nt++)
#pragma unroll
        for (int j = 0; j < 4; j++) d[nt][j] = 0.f;

#pragma unroll
    for (int ks = 0; ks < 16; ks++) {
        int k0 = ks * 8;
        // A fragments (m16k8, row-major): rows rb+gid / rb+gid+8, cols k0+tg / k0+tg+4
        float af0 = Hs[(rb + gid) * SW + k0 + tg];
        float af1 = Hs[(rb + gid + 8) * SW + k0 + tg];
        float af2 = Hs[(rb + gid) * SW + k0 + tg + 4];
        float af3 = Hs[(rb + gid + 8) * SW + k0 + tg + 4];
        float ah0 = to_tf32(af0), ah1 = to_tf32(af1), ah2 = to_tf32(af2), ah3 = to_tf32(af3);
        uint32_t h0 = __float_as_uint(ah0), h1 = __float_as_uint(ah1);
        uint32_t h2 = __float_as_uint(ah2), h3 = __float_as_uint(ah3);
        uint32_t l0 = __float_as_uint(to_tf32(af0 - ah0));
        uint32_t l1 = __float_as_uint(to_tf32(af1 - ah1));
        uint32_t l2 = __float_as_uint(to_tf32(af2 - ah2));
        uint32_t l3 = __float_as_uint(to_tf32(af3 - ah3));

#pragma unroll
        for (int nt = 0; nt < 16; nt++) {
            int n0 = nt * 8;
            // B fragments (k8n8, B[k][n]): k = k0+tg / k0+tg+4, n = n0+gid
            uint32_t bh0 = __float_as_uint(Whs[(k0 + tg) * SW + n0 + gid]);
            uint32_t bh1 = __float_as_uint(Whs[(k0 + tg + 4) * SW + n0 + gid]);
            uint32_t bl0 = __float_as_uint(Wls[(k0 + tg) * SW + n0 + gid]);
            uint32_t bl1 = __float_as_uint(Wls[(k0 + tg + 4) * SW + n0 + gid]);
            mma_tf32(d[nt][0], d[nt][1], d[nt][2], d[nt][3], h0, h1, h2, h3, bh0, bh1);
            mma_tf32(d[nt][0], d[nt][1], d[nt][2], d[nt][3], h0, h1, h2, h3, bl0, bl1);
            mma_tf32(d[nt][0], d[nt][1], d[nt][2], d[nt][3], l0, l1, l2, l3, bh0, bh1);
        }
    }

    // epilogue: c0/c1 -> row gid, cols 2tg/2tg+1 ; c2/c3 -> row gid+8
    int rA = row0 + rb + gid;
    int rB = rA + 8;
#pragma unroll
    for (int nt = 0; nt < 16; nt++) {
        int col = nt * 8 + tg * 2;
        float b0 = Bs[col], b1 = Bs[col + 1];
        if (rA < NN) {
            float2 o = make_float2(d[nt][0] + b0, d[nt][1] + b1);
            reinterpret_cast<float2*>(out + (size_t)rA * F + col)[0] = o;
        }
        if (rB < NN) {
            float2 o = make_float2(d[nt][2] + b0, d[nt][3] + b1);
            reinterpret_cast<float2*>(out + (size_t)rB * F + col)[0] = o;
        }
    }
}

// ---------------------------------------------------------------------------
extern "C" void kernel_launch(void* const* d_in, const int* in_sizes, int n_in,
                              void* d_out, int out_size) {
    const float* x      = (const float*)d_in[0];
    const int*   src    = (const int*)d_in[1];
    const int*   dst    = (const int*)d_in[2];
    const float* weight = (const float*)d_in[3];
    const float* bias   = (const float*)d_in[4];
    float*       out    = (float*)d_out;

    wsplit_kernel<<<(F * F + 255) / 256, 256>>>(weight);
    zero_kernel<<<(NN + 255) / 256, 256>>>();
    deg_kernel<<<(NE + 255) / 256, 256>>>(src, dst);
    scan1_kernel<<<NBLK, SCAN_B>>>();
    scan2_kernel<<<1, SCAN_B>>>();
    scan3_kernel<<<NBLK, SCAN_B>>>();
    scatter_kernel<<<((NE + 1) / 2 + 255) / 256, 256>>>(src, dst);

    {
        long long threads = (long long)NN * 32;
        int blocks = (int)((threads + 255) / 256);
        agg_kernel<<<blocks, 256>>>(x);
    }
    {
        int smem = (2 * F * SW + BM * SW + F) * (int)sizeof(float);  // 203264 B
        cudaFuncSetAttribute(gemm_tc_kernel, cudaFuncAttributeMaxDynamicSharedMemorySize, smem);
        gemm_tc_kernel<<<(NN + BM - 1) / BM, 256, smem>>>(bias, out);
    }
}